// round 12
// baseline (speedup 1.0000x reference)
#include <cuda_runtime.h>
#include <cuda_fp16.h>
#include <cstdint>

// ---------------------------------------------------------------------------
// S6 block, legacy mma.sync path (tcgen05 unavailable on this build).
// Single-term fp16 GEMMs (m16n8k16.f32.f16.f16.f32 — the only full-rate mma
// on this pipe; fp8 k32=2x cycles, int8 k32=4x, measured R7/R10).
// gemm1: fp16, fused S6 elementwise + per-64-row-chunk scan aggregates;
//        epilogue staged through smem for fully coalesced global writes.
// scan2: chunk prefix. gemm2f: per-chunk CTA scans in its prologue, holds the
// fp16 y operand in resident smem (66KB -> 2 CTAs/SM), streams Wy.
// Shapes fixed: B=4, L=4096, Cin=256, N=512, Cout=256.
// ---------------------------------------------------------------------------

constexpr int kBL = 16384, kN = 512, kCout = 256, kL = 4096, kB = 4;
constexpr int kCH = 64;                          // rows per chunk
constexpr int kNCHUNK = kBL / kCH;               // 256 chunks

// ------------------------- scratch (device globals) ------------------------
__device__ __half g_xp [(size_t)kBL * 256];      // fp16 x, [row][256]
__device__ __half g_Wp1[(size_t)256 * 2048];     // fp16 W1, [k][jperm]
__device__ __half g_Wyp[(size_t)512 * 256];      // fp16 Wy, [k][j]
__device__ float2 g_au[(size_t)kBL * kN];        // (a, u) per element
__device__ float  g_c [(size_t)kBL * kN];
__device__ float2 g_AB[kNCHUNK * kN];            // per-chunk (A~, B~)
__device__ float  g_H [kNCHUNK * kN];            // chunk-start h

__device__ __forceinline__ uint32_t smem_u32(const void* p) {
    return (uint32_t)__cvta_generic_to_shared(p);
}

// ------------------------------ pack kernels --------------------------------
__global__ void pack_x_kernel(const float* __restrict__ x) {
    int idx = blockIdx.x * 256 + threadIdx.x;            // kBL*64 total
    int row = idx >> 6, k4 = (idx & 63) << 2;
    float4 v = *(const float4*)(x + (size_t)row * 256 + k4);
    __half2 h01 = __floats2half2_rn(v.x, v.y);
    __half2 h23 = __floats2half2_rn(v.z, v.w);
    __half2* ph = (__half2*)(g_xp + (size_t)row * 256 + k4);
    ph[0] = h01;
    ph[1] = h23;
}

// Permuted W1 columns. For j = n128*128 + w*32 + nf*8 + q2*2 + r:
//   group g = n128*32 + w*8 + (nf>>1)*4 + q2,  member m = (nf&1)*2 + r
//   m: 0=Wx[:,g] 1=Wbc[:,g] 2=Wbc[:,512+g] 3=Wd[:,g]
__global__ void pack_w1_kernel(const float* __restrict__ Wx,
                               const float* __restrict__ Wbc,
                               const float* __restrict__ Wd) {
    int idx = blockIdx.x * 256 + threadIdx.x;            // 256*2048 total
    int k = idx >> 11, j = idx & 2047;
    int g = (j >> 7) * 32 + ((j >> 5) & 3) * 8 + ((j >> 4) & 1) * 4 + ((j >> 1) & 3);
    int m = ((j >> 3) & 1) * 2 + (j & 1);
    float w;
    if (m == 0)      w = Wx [k * 512  + g];
    else if (m == 1) w = Wbc[k * 1024 + g];
    else if (m == 2) w = Wbc[k * 1024 + 512 + g];
    else             w = Wd [k * 512  + g];
    g_Wp1[(size_t)k * 2048 + j] = __float2half_rn(w);
}

__global__ void pack_wy_kernel(const float* __restrict__ Wy) {
    int idx = blockIdx.x * 256 + threadIdx.x;            // 512*256 total
    g_Wyp[idx] = __float2half_rn(Wy[idx]);
}

// ----------------------------- gemm1 (fp16) ---------------------------------
// CTA 128x128 out, 8 warps of 64x32, k-tile 32 elems, 4-stage cp.async.
#define STAGES 4
constexpr int A_STB = 128 * 80;                  // 128 rows x (64B + 16 pad)
constexpr int B_STB = 32 * 272;                  // 32 k-rows x (256B + 16 pad)
constexpr int GEMM1_SMEM = STAGES * (A_STB + B_STB);      // 75776

__global__ void __launch_bounds__(256, 2)
gemm1_fused(const __half* __restrict__ AH,       // [row][256]
            const __half* __restrict__ BH,       // [k][2048]
            const float* __restrict__ bx, const float* __restrict__ bbc,
            const float* __restrict__ bd) {
    extern __shared__ __align__(16) char smc[];
    char* As = smc;
    char* Bs = smc + STAGES * A_STB;

    constexpr int KT = 8;                        // 256 / 32
    constexpr int ASTR = 512;                    // bytes per A row
    constexpr int BSTR = 4096;                   // bytes per B k-row

    const int tid = threadIdx.x, lane = tid & 31, warp = tid >> 5;
    const int wm = (warp >> 2) * 64, wn = (warp & 3) * 32;
    const int bm = blockIdx.y * 128, bn = blockIdx.x * 128;

    float acc[4][4][4];
#pragma unroll
    for (int i = 0; i < 4; i++)
#pragma unroll
        for (int j = 0; j < 4; j++)
#pragma unroll
            for (int q = 0; q < 4; q++) acc[i][j][q] = 0.f;

    auto load_tile = [&](int kt, int st) {
        const char* Ab = (const char*)AH + kt * 64;
        const char* Bb = (const char*)BH + (size_t)(kt * 32) * BSTR;
        char* as = As + st * A_STB;
#pragma unroll
        for (int i = 0; i < 2; i++) {            // A: 128 rows x 4 x16B
            int c = tid + i * 256;
            int row = c >> 2, sg = c & 3;
            asm volatile("cp.async.cg.shared.global [%0], [%1], 16;" ::
                         "r"(smem_u32(as + row * 80 + sg * 16)),
                         "l"(Ab + (size_t)(bm + row) * ASTR + sg * 16));
        }
        char* bs = Bs + st * B_STB;
#pragma unroll
        for (int i = 0; i < 2; i++) {            // B: 32 rows x 16 x16B
            int c = tid + i * 256;
            int row = c >> 4, sg = c & 15;
            asm volatile("cp.async.cg.shared.global [%0], [%1], 16;" ::
                         "r"(smem_u32(bs + row * 272 + sg * 16)),
                         "l"(Bb + (size_t)row * BSTR + bn * 2 + sg * 16));
        }
        asm volatile("cp.async.commit_group;");
    };

    load_tile(0, 0);
    load_tile(1, 1);
    load_tile(2, 2);

#pragma unroll 1
    for (int kt = 0; kt < KT; kt++) {
        int s = kt & 3;
        if (kt + 2 < KT)      asm volatile("cp.async.wait_group 2;");
        else if (kt + 1 < KT) asm volatile("cp.async.wait_group 1;");
        else                  asm volatile("cp.async.wait_group 0;");
        __syncthreads();
        if (kt + 3 < KT) load_tile(kt + 3, (kt + 3) & 3);

        char* as = As + s * A_STB;
        char* bs = Bs + s * B_STB;
#pragma unroll
        for (int ks = 0; ks < 2; ks++) {
            uint32_t af[4][4];
            uint32_t bf[4][2];
#pragma unroll
            for (int mf = 0; mf < 4; mf++) {
                uint32_t addr = smem_u32(
                    as + (wm + mf * 16 + (lane & 15)) * 80 + ks * 32 + (lane >> 4) * 16);
                asm volatile(
                    "ldmatrix.sync.aligned.m8n8.x4.shared.b16 {%0,%1,%2,%3}, [%4];\n"
                    : "=r"(af[mf][0]), "=r"(af[mf][1]), "=r"(af[mf][2]), "=r"(af[mf][3])
                    : "r"(addr));
            }
#pragma unroll
            for (int p = 0; p < 2; p++) {
                uint32_t addr = smem_u32(
                    bs + (ks * 16 + (lane & 15)) * 272 + (wn + p * 16 + (lane >> 4) * 8) * 2);
                uint32_t r0, r1, r2, r3;
                asm volatile(
                    "ldmatrix.sync.aligned.m8n8.x4.trans.shared.b16 {%0,%1,%2,%3}, [%4];\n"
                    : "=r"(r0), "=r"(r1), "=r"(r2), "=r"(r3)
                    : "r"(addr));
                bf[p * 2][0] = r0;     bf[p * 2][1] = r1;
                bf[p * 2 + 1][0] = r2; bf[p * 2 + 1][1] = r3;
            }
#pragma unroll
            for (int mf = 0; mf < 4; mf++) {
#pragma unroll
                for (int nf = 0; nf < 4; nf++) {
                    asm volatile(
                        "mma.sync.aligned.m16n8k16.row.col.f32.f16.f16.f32 "
                        "{%0,%1,%2,%3}, {%4,%5,%6,%7}, {%8,%9}, {%0,%1,%2,%3};\n"
                        : "+f"(acc[mf][nf][0]), "+f"(acc[mf][nf][1]),
                          "+f"(acc[mf][nf][2]), "+f"(acc[mf][nf][3])
                        : "r"(af[mf][0]), "r"(af[mf][1]), "r"(af[mf][2]), "r"(af[mf][3]),
                          "r"(bf[nf][0]), "r"(bf[nf][1]));
                }
            }
        }
    }

    // ---- Fused S6 elementwise + per-64-row-chunk scan aggregates ----
    // Values staged in smem [128][33] (pad kills bank conflicts), then
    // written out fully coalesced. Aggregates via register shuffles.
    __syncthreads();                              // mainloop smem dead now
    float* sm_a = (float*)smc;                    // [128][33]
    float* sm_u = sm_a + 128 * 33;
    float* sm_c = sm_u + 128 * 33;                // total 50688 B

    const int gbase = (bn >> 2) + (wn >> 2) + (lane & 3);   // global group
    const int glb   = (warp & 3) * 8 + (lane & 3);          // local group
    const int chunk = blockIdx.y * 2 + (warp >> 2);
#pragma unroll
    for (int t2 = 0; t2 < 2; t2++) {
        int g  = gbase + t2 * 4;
        int gl = glb + t2 * 4;
        float vbx = bx[g], vbb = bbc[g], vbc = bbc[512 + g], vbd = bd[g];
        float At = 1.f, Bt = 0.f;
#pragma unroll
        for (int mf = 0; mf < 4; mf++) {
#pragma unroll
            for (int h = 0; h < 2; h++) {
                int rl = wm + mf * 16 + h * 8 + (lane >> 2);   // local row
                float xv = acc[mf][2 * t2 + 0][h * 2 + 0] + vbx;
                float bv = acc[mf][2 * t2 + 0][h * 2 + 1] + vbb;
                float cc = acc[mf][2 * t2 + 1][h * 2 + 0] + vbc;
                float dd = acc[mf][2 * t2 + 1][h * 2 + 1] + vbd;
                float Aa = 1.0f / (1.0f + expf(dd));
                float uu = (1.0f - Aa) * bv * xv;
                sm_a[rl * 33 + gl] = Aa;
                sm_u[rl * 33 + gl] = uu;
                sm_c[rl * 33 + gl] = cc;
                float A1 = Aa, B1 = uu;
#pragma unroll
                for (int st = 4; st <= 16; st <<= 1) {
                    float pa = __shfl_xor_sync(0xffffffffu, A1, st);
                    float pb = __shfl_xor_sync(0xffffffffu, B1, st);
                    if ((lane & st) == 0) {
                        B1 = pa * B1 + pb;
                        A1 = A1 * pa;
                    } else {
                        B1 = A1 * pb + B1;
                        A1 = pa * A1;
                    }
                }
                Bt = A1 * Bt + B1;
                At = At * A1;
            }
        }
        if ((lane >> 2) == 0) g_AB[chunk * kN + g] = make_float2(At, Bt);
    }
    __syncthreads();

    // coalesced writeout: 32 consecutive channels per warp
    const int gblock = bn >> 2;
#pragma unroll
    for (int i = tid; i < 128 * 32; i += 256) {
        int row = i >> 5, col = i & 31;
        float av = sm_a[row * 33 + col];
        float uv = sm_u[row * 33 + col];
        size_t o = (size_t)(bm + row) * kN + gblock + col;
        g_au[o] = make_float2(av, uv);
        g_c[o]  = sm_c[row * 33 + col];
    }
}

// ------------------------------- chunk prefix -------------------------------
__global__ void scan_phase2() {
    int b = blockIdx.x >> 1;
    int n = (blockIdx.x & 1) * 256 + threadIdx.x;
    int base = b * 64;
    float2 buf[4];
#pragma unroll
    for (int i = 0; i < 4; i++) buf[i] = g_AB[(base + i) * kN + n];
    float h = 0.f;
#pragma unroll 4
    for (int ch = 0; ch < 64; ch++) {
        float2 cur = buf[ch & 3];
        if (ch + 4 < 64) buf[ch & 3] = g_AB[(base + ch + 4) * kN + n];
        g_H[(base + ch) * kN + n] = h;
        h = fmaf(cur.x, h, cur.y);
    }
}

// ------------------- gemm2f: fused scan + output GEMM -----------------------
// One CTA per 64-row chunk. Prologue: scan 64 steps, write fp16 y operand
// into resident smem (66.5KB). Mainloop: single-term fp16, A resident,
// Wy streamed via 4-stage 16-k-row tiles -> 100KB total, 2 CTAs/SM.
constexpr int AROWE = 520;                       // 512 elems + 8 pad
constexpr int A2_BYTES = 64 * AROWE * 2;         // 66560
constexpr int B2ROW = 264;
constexpr int B2_ST = 16 * B2ROW;                // elems per stage (4224)
constexpr int GEMM2_SMEM = A2_BYTES + STAGES * B2_ST * 2;   // 100352

__global__ void __launch_bounds__(256, 2)
gemm2f(const __half* __restrict__ Bw,            // g_Wyp [512][256]
       const float* __restrict__ bias,
       float* __restrict__ Cout_) {
    extern __shared__ __align__(16) char smc[];
    __half* As = (__half*)smc;
    __half* Bs = (__half*)(smc + A2_BYTES);

    constexpr int KT = 32;                       // 512 / 16
    const int tid = threadIdx.x, lane = tid & 31, warp = tid >> 5;
    const int wn = warp * 32;
    const int chunk = blockIdx.x;
    const int row0 = chunk * 64;

    auto load_B = [&](int kt, int st) {
        const __half* Bb = Bw + (size_t)(kt * 16) * 256;
        __half* bs = Bs + st * B2_ST;
#pragma unroll
        for (int i = 0; i < 2; i++) {            // 16 rows x 32 chunks of 8
            int c = tid + i * 256;
            int row = c >> 5, sg = c & 31;
            asm volatile("cp.async.cg.shared.global [%0], [%1], 16;" ::
                         "r"(smem_u32(bs + row * B2ROW + sg * 8)),
                         "l"(Bb + (size_t)row * 256 + sg * 8));
        }
        asm volatile("cp.async.commit_group;");
    };

    // issue first B stages, then run the scan while they fly
    load_B(0, 0);
    load_B(1, 1);
    load_B(2, 2);

    {   // scan prologue: 64 steps, 2 channels per thread
        int n = tid * 2;
        float2 h2 = *(const float2*)(g_H + chunk * kN + n);
#pragma unroll 4
        for (int t = 0; t < 64; t++) {
            size_t o = (size_t)(row0 + t) * kN + n;
            float4 au = *(const float4*)(g_au + o);       // (a0,u0,a1,u1)
            float2 c2 = *(const float2*)(g_c + o);
            h2.x = fmaf(au.x, h2.x, au.y);
            h2.y = fmaf(au.z, h2.y, au.w);
            *(__half2*)(As + t * AROWE + n) =
                __floats2half2_rn(c2.x * h2.x, c2.y * h2.y);
        }
    }
    __syncthreads();                              // A operand ready

    float acc[4][4][4];
#pragma unroll
    for (int i = 0; i < 4; i++)
#pragma unroll
        for (int j = 0; j < 4; j++)
#pragma unroll
            for (int q = 0; q < 4; q++) acc[i][j][q] = 0.f;

#pragma unroll 1
    for (int kt = 0; kt < KT; kt++) {
        int s = kt & 3;
        if (kt + 2 < KT)      asm volatile("cp.async.wait_group 2;");
        else if (kt + 1 < KT) asm volatile("cp.async.wait_group 1;");
        else                  asm volatile("cp.async.wait_group 0;");
        __syncthreads();
        if (kt + 3 < KT) load_B(kt + 3, (kt + 3) & 3);

        int aoff = kt * 16;
        __half* bs = Bs + s * B2_ST;
        uint32_t af[4][4];
        uint32_t bf[4][2];
#pragma unroll
        for (int mf = 0; mf < 4; mf++) {
            uint32_t addr = smem_u32(
                As + (mf * 16 + (lane & 15)) * AROWE + aoff + (lane >> 4) * 8);
            asm volatile(
                "ldmatrix.sync.aligned.m8n8.x4.shared.b16 {%0,%1,%2,%3}, [%4];\n"
                : "=r"(af[mf][0]), "=r"(af[mf][1]), "=r"(af[mf][2]), "=r"(af[mf][3])
                : "r"(addr));
        }
#pragma unroll
        for (int p = 0; p < 2; p++) {
            uint32_t addr = smem_u32(
                bs + (lane & 15) * B2ROW + wn + p * 16 + (lane >> 4) * 8);
            uint32_t r0, r1, r2, r3;
            asm volatile(
                "ldmatrix.sync.aligned.m8n8.x4.trans.shared.b16 {%0,%1,%2,%3}, [%4];\n"
                : "=r"(r0), "=r"(r1), "=r"(r2), "=r"(r3)
                : "r"(addr));
            bf[p * 2][0] = r0;     bf[p * 2][1] = r1;
            bf[p * 2 + 1][0] = r2; bf[p * 2 + 1][1] = r3;
        }
#pragma unroll
        for (int mf = 0; mf < 4; mf++) {
#pragma unroll
            for (int nf = 0; nf < 4; nf++) {
                asm volatile(
                    "mma.sync.aligned.m16n8k16.row.col.f32.f16.f16.f32 "
                    "{%0,%1,%2,%3}, {%4,%5,%6,%7}, {%8,%9}, {%0,%1,%2,%3};\n"
                    : "+f"(acc[mf][nf][0]), "+f"(acc[mf][nf][1]),
                      "+f"(acc[mf][nf][2]), "+f"(acc[mf][nf][3])
                    : "r"(af[mf][0]), "r"(af[mf][1]), "r"(af[mf][2]), "r"(af[mf][3]),
                      "r"(bf[nf][0]), "r"(bf[nf][1]));
            }
        }
    }

#pragma unroll
    for (int mf = 0; mf < 4; mf++) {
#pragma unroll
        for (int nf = 0; nf < 4; nf++) {
            int row = row0 + mf * 16 + (lane >> 2);
            int col = wn + nf * 8 + (lane & 3) * 2;
            float b0 = bias[col], b1 = bias[col + 1];
            *reinterpret_cast<float2*>(Cout_ + (size_t)row * kCout + col) =
                make_float2(acc[mf][nf][0] + b0, acc[mf][nf][1] + b1);
            *reinterpret_cast<float2*>(Cout_ + (size_t)(row + 8) * kCout + col) =
                make_float2(acc[mf][nf][2] + b0, acc[mf][nf][3] + b1);
        }
    }
}

// --------------------------------- launcher ---------------------------------
extern "C" void kernel_launch(void* const* d_in, const int* in_sizes, int n_in,
                              void* d_out, int out_size) {
    const float* x   = (const float*)d_in[0];
    const float* Wx  = (const float*)d_in[1];
    const float* bx  = (const float*)d_in[2];
    const float* Wbc = (const float*)d_in[3];
    const float* bbc = (const float*)d_in[4];
    const float* Wd  = (const float*)d_in[5];
    const float* bd  = (const float*)d_in[6];
    const float* Wy  = (const float*)d_in[7];
    const float* by  = (const float*)d_in[8];
    float* out = (float*)d_out;
    (void)in_sizes; (void)n_in; (void)out_size;

    void *p_xp, *p_wp1, *p_wyp;
    cudaGetSymbolAddress(&p_xp,  g_xp);
    cudaGetSymbolAddress(&p_wp1, g_Wp1);
    cudaGetSymbolAddress(&p_wyp, g_Wyp);

    cudaFuncSetAttribute(gemm1_fused, cudaFuncAttributeMaxDynamicSharedMemorySize, GEMM1_SMEM);
    cudaFuncSetAttribute(gemm2f,      cudaFuncAttributeMaxDynamicSharedMemorySize, GEMM2_SMEM);

    pack_x_kernel <<<(kBL * 64) / 256, 256>>>(x);
    pack_w1_kernel<<<(256 * 2048) / 256, 256>>>(Wx, Wbc, Wd);
    pack_wy_kernel<<<(512 * 256) / 256, 256>>>(Wy);

    gemm1_fused<<<dim3(16, 128), 256, GEMM1_SMEM>>>(
        (const __half*)p_xp, (const __half*)p_wp1, bx, bbc, bd);

    scan_phase2<<<8, 256>>>();

    gemm2f<<<kNCHUNK, 256, GEMM2_SMEM>>>(
        (const __half*)p_wyp, by, out);
}

// round 13
// speedup vs baseline: 1.1318x; 1.1318x over previous
#include <cuda_runtime.h>
#include <cuda_fp16.h>
#include <cstdint>

// ---------------------------------------------------------------------------
// S6 block, legacy mma.sync path (tcgen05 unavailable on this build).
// Single-term fp16 GEMMs (m16n8k16.f32.f16.f16.f32 — the only full-rate mma
// on this pipe; fp8 k32=2x cycles, int8 k32=4x, measured R7/R10).
// gemm1: fp16, fused S6 elementwise + per-64-row-chunk scan aggregates
//        (direct-scatter epilogue — R12's smem staging regressed, reverted).
// c stored fp16 (y is fp16-quantized downstream anyway). scan2: chunk prefix
// with 8-deep prefetch. gemm2f: per-chunk CTA scans in its prologue, holds
// the fp16 y operand in resident smem (66KB -> 2 CTAs/SM), streams Wy.
// Shapes fixed: B=4, L=4096, Cin=256, N=512, Cout=256.
// ---------------------------------------------------------------------------

constexpr int kBL = 16384, kN = 512, kCout = 256, kL = 4096, kB = 4;
constexpr int kCH = 64;                          // rows per chunk
constexpr int kNCHUNK = kBL / kCH;               // 256 chunks

// ------------------------- scratch (device globals) ------------------------
__device__ __half g_xp [(size_t)kBL * 256];      // fp16 x, [row][256]
__device__ __half g_Wp1[(size_t)256 * 2048];     // fp16 W1, [k][jperm]
__device__ __half g_Wyp[(size_t)512 * 256];      // fp16 Wy, [k][j]
__device__ float2 g_au[(size_t)kBL * kN];        // (a, u) per element
__device__ __half g_ch[(size_t)kBL * kN];        // c per element (fp16)
__device__ float2 g_AB[kNCHUNK * kN];            // per-chunk (A~, B~)
__device__ float  g_H [kNCHUNK * kN];            // chunk-start h

__device__ __forceinline__ uint32_t smem_u32(const void* p) {
    return (uint32_t)__cvta_generic_to_shared(p);
}

// ------------------------------ pack kernels --------------------------------
__global__ void pack_x_kernel(const float* __restrict__ x) {
    int idx = blockIdx.x * 256 + threadIdx.x;            // kBL*64 total
    int row = idx >> 6, k4 = (idx & 63) << 2;
    float4 v = *(const float4*)(x + (size_t)row * 256 + k4);
    __half2 h01 = __floats2half2_rn(v.x, v.y);
    __half2 h23 = __floats2half2_rn(v.z, v.w);
    __half2* ph = (__half2*)(g_xp + (size_t)row * 256 + k4);
    ph[0] = h01;
    ph[1] = h23;
}

// Permuted W1 columns. For j = n128*128 + w*32 + nf*8 + q2*2 + r:
//   group g = n128*32 + w*8 + (nf>>1)*4 + q2,  member m = (nf&1)*2 + r
//   m: 0=Wx[:,g] 1=Wbc[:,g] 2=Wbc[:,512+g] 3=Wd[:,g]
__global__ void pack_w1_kernel(const float* __restrict__ Wx,
                               const float* __restrict__ Wbc,
                               const float* __restrict__ Wd) {
    int idx = blockIdx.x * 256 + threadIdx.x;            // 256*2048 total
    int k = idx >> 11, j = idx & 2047;
    int g = (j >> 7) * 32 + ((j >> 5) & 3) * 8 + ((j >> 4) & 1) * 4 + ((j >> 1) & 3);
    int m = ((j >> 3) & 1) * 2 + (j & 1);
    float w;
    if (m == 0)      w = Wx [k * 512  + g];
    else if (m == 1) w = Wbc[k * 1024 + g];
    else if (m == 2) w = Wbc[k * 1024 + 512 + g];
    else             w = Wd [k * 512  + g];
    g_Wp1[(size_t)k * 2048 + j] = __float2half_rn(w);
}

__global__ void pack_wy_kernel(const float* __restrict__ Wy) {
    int idx = blockIdx.x * 256 + threadIdx.x;            // 512*256 total
    g_Wyp[idx] = __float2half_rn(Wy[idx]);
}

// ----------------------------- gemm1 (fp16) ---------------------------------
// CTA 128x128 out, 8 warps of 64x32, k-tile 32 elems, 4-stage cp.async.
#define STAGES 4
constexpr int A_STB = 128 * 80;                  // 128 rows x (64B + 16 pad)
constexpr int B_STB = 32 * 272;                  // 32 k-rows x (256B + 16 pad)
constexpr int GEMM1_SMEM = STAGES * (A_STB + B_STB);      // 75776

__global__ void __launch_bounds__(256, 2)
gemm1_fused(const __half* __restrict__ AH,       // [row][256]
            const __half* __restrict__ BH,       // [k][2048]
            const float* __restrict__ bx, const float* __restrict__ bbc,
            const float* __restrict__ bd) {
    extern __shared__ __align__(16) char smc[];
    char* As = smc;
    char* Bs = smc + STAGES * A_STB;

    constexpr int KT = 8;                        // 256 / 32
    constexpr int ASTR = 512;                    // bytes per A row
    constexpr int BSTR = 4096;                   // bytes per B k-row

    const int tid = threadIdx.x, lane = tid & 31, warp = tid >> 5;
    const int wm = (warp >> 2) * 64, wn = (warp & 3) * 32;
    const int bm = blockIdx.y * 128, bn = blockIdx.x * 128;

    float acc[4][4][4];
#pragma unroll
    for (int i = 0; i < 4; i++)
#pragma unroll
        for (int j = 0; j < 4; j++)
#pragma unroll
            for (int q = 0; q < 4; q++) acc[i][j][q] = 0.f;

    auto load_tile = [&](int kt, int st) {
        const char* Ab = (const char*)AH + kt * 64;
        const char* Bb = (const char*)BH + (size_t)(kt * 32) * BSTR;
        char* as = As + st * A_STB;
#pragma unroll
        for (int i = 0; i < 2; i++) {            // A: 128 rows x 4 x16B
            int c = tid + i * 256;
            int row = c >> 2, sg = c & 3;
            asm volatile("cp.async.cg.shared.global [%0], [%1], 16;" ::
                         "r"(smem_u32(as + row * 80 + sg * 16)),
                         "l"(Ab + (size_t)(bm + row) * ASTR + sg * 16));
        }
        char* bs = Bs + st * B_STB;
#pragma unroll
        for (int i = 0; i < 2; i++) {            // B: 32 rows x 16 x16B
            int c = tid + i * 256;
            int row = c >> 4, sg = c & 15;
            asm volatile("cp.async.cg.shared.global [%0], [%1], 16;" ::
                         "r"(smem_u32(bs + row * 272 + sg * 16)),
                         "l"(Bb + (size_t)row * BSTR + bn * 2 + sg * 16));
        }
        asm volatile("cp.async.commit_group;");
    };

    load_tile(0, 0);
    load_tile(1, 1);
    load_tile(2, 2);

#pragma unroll 1
    for (int kt = 0; kt < KT; kt++) {
        int s = kt & 3;
        if (kt + 2 < KT)      asm volatile("cp.async.wait_group 2;");
        else if (kt + 1 < KT) asm volatile("cp.async.wait_group 1;");
        else                  asm volatile("cp.async.wait_group 0;");
        __syncthreads();
        if (kt + 3 < KT) load_tile(kt + 3, (kt + 3) & 3);

        char* as = As + s * A_STB;
        char* bs = Bs + s * B_STB;
#pragma unroll
        for (int ks = 0; ks < 2; ks++) {
            uint32_t af[4][4];
            uint32_t bf[4][2];
#pragma unroll
            for (int mf = 0; mf < 4; mf++) {
                uint32_t addr = smem_u32(
                    as + (wm + mf * 16 + (lane & 15)) * 80 + ks * 32 + (lane >> 4) * 16);
                asm volatile(
                    "ldmatrix.sync.aligned.m8n8.x4.shared.b16 {%0,%1,%2,%3}, [%4];\n"
                    : "=r"(af[mf][0]), "=r"(af[mf][1]), "=r"(af[mf][2]), "=r"(af[mf][3])
                    : "r"(addr));
            }
#pragma unroll
            for (int p = 0; p < 2; p++) {
                uint32_t addr = smem_u32(
                    bs + (ks * 16 + (lane & 15)) * 272 + (wn + p * 16 + (lane >> 4) * 8) * 2);
                uint32_t r0, r1, r2, r3;
                asm volatile(
                    "ldmatrix.sync.aligned.m8n8.x4.trans.shared.b16 {%0,%1,%2,%3}, [%4];\n"
                    : "=r"(r0), "=r"(r1), "=r"(r2), "=r"(r3)
                    : "r"(addr));
                bf[p * 2][0] = r0;     bf[p * 2][1] = r1;
                bf[p * 2 + 1][0] = r2; bf[p * 2 + 1][1] = r3;
            }
#pragma unroll
            for (int mf = 0; mf < 4; mf++) {
#pragma unroll
                for (int nf = 0; nf < 4; nf++) {
                    asm volatile(
                        "mma.sync.aligned.m16n8k16.row.col.f32.f16.f16.f32 "
                        "{%0,%1,%2,%3}, {%4,%5,%6,%7}, {%8,%9}, {%0,%1,%2,%3};\n"
                        : "+f"(acc[mf][nf][0]), "+f"(acc[mf][nf][1]),
                          "+f"(acc[mf][nf][2]), "+f"(acc[mf][nf][3])
                        : "r"(af[mf][0]), "r"(af[mf][1]), "r"(af[mf][2]), "r"(af[mf][3]),
                          "r"(bf[nf][0]), "r"(bf[nf][1]));
                }
            }
        }
    }

    // Fused S6 elementwise + per-64-row-chunk scan aggregates.
    // Warp-row (warps 0-3 -> rows 0..63, warps 4-7 -> 64..127) == one chunk.
    const int gbase = (bn >> 2) + (wn >> 2) + (lane & 3);
    const int chunk = blockIdx.y * 2 + (warp >> 2);
#pragma unroll
    for (int t2 = 0; t2 < 2; t2++) {
        int g = gbase + t2 * 4;
        float vbx = bx[g], vbb = bbc[g], vbc = bbc[512 + g], vbd = bd[g];
        float At = 1.f, Bt = 0.f;
#pragma unroll
        for (int mf = 0; mf < 4; mf++) {
#pragma unroll
            for (int h = 0; h < 2; h++) {
                int R = bm + wm + mf * 16 + h * 8 + (lane >> 2);
                float xv = acc[mf][2 * t2 + 0][h * 2 + 0] + vbx;
                float bv = acc[mf][2 * t2 + 0][h * 2 + 1] + vbb;
                float cc = acc[mf][2 * t2 + 1][h * 2 + 0] + vbc;
                float dd = acc[mf][2 * t2 + 1][h * 2 + 1] + vbd;
                float Aa = 1.0f / (1.0f + expf(dd));
                float uu = (1.0f - Aa) * bv * xv;
                size_t o = (size_t)R * kN + g;
                g_au[o] = make_float2(Aa, uu);
                g_ch[o] = __float2half_rn(cc);
                float A1 = Aa, B1 = uu;
#pragma unroll
                for (int st = 4; st <= 16; st <<= 1) {
                    float pa = __shfl_xor_sync(0xffffffffu, A1, st);
                    float pb = __shfl_xor_sync(0xffffffffu, B1, st);
                    if ((lane & st) == 0) {
                        B1 = pa * B1 + pb;
                        A1 = A1 * pa;
                    } else {
                        B1 = A1 * pb + B1;
                        A1 = pa * A1;
                    }
                }
                Bt = A1 * Bt + B1;
                At = At * A1;
            }
        }
        if ((lane >> 2) == 0) g_AB[chunk * kN + g] = make_float2(At, Bt);
    }
}

// ------------------------------- chunk prefix -------------------------------
__global__ void scan_phase2() {
    int b = blockIdx.x >> 1;
    int n = (blockIdx.x & 1) * 256 + threadIdx.x;
    int base = b * 64;
    float2 buf[8];
#pragma unroll
    for (int i = 0; i < 8; i++) buf[i] = g_AB[(base + i) * kN + n];
    float h = 0.f;
#pragma unroll 8
    for (int ch = 0; ch < 64; ch++) {
        float2 cur = buf[ch & 7];
        if (ch + 8 < 64) buf[ch & 7] = g_AB[(base + ch + 8) * kN + n];
        g_H[(base + ch) * kN + n] = h;
        h = fmaf(cur.x, h, cur.y);
    }
}

// ------------------- gemm2f: fused scan + output GEMM -----------------------
// One CTA per 64-row chunk. Prologue: scan 64 steps, write fp16 y operand
// into resident smem (66.5KB). Mainloop: single-term fp16, A resident,
// Wy streamed via 4-stage 16-k-row tiles -> 100KB total, 2 CTAs/SM.
constexpr int AROWE = 520;                       // 512 elems + 8 pad
constexpr int A2_BYTES = 64 * AROWE * 2;         // 66560
constexpr int B2ROW = 264;
constexpr int B2_ST = 16 * B2ROW;                // elems per stage (4224)
constexpr int GEMM2_SMEM = A2_BYTES + STAGES * B2_ST * 2;   // 100352

__global__ void __launch_bounds__(256, 2)
gemm2f(const __half* __restrict__ Bw,            // g_Wyp [512][256]
       const float* __restrict__ bias,
       float* __restrict__ Cout_) {
    extern __shared__ __align__(16) char smc[];
    __half* As = (__half*)smc;
    __half* Bs = (__half*)(smc + A2_BYTES);

    constexpr int KT = 32;                       // 512 / 16
    const int tid = threadIdx.x, lane = tid & 31, warp = tid >> 5;
    const int wn = warp * 32;
    const int chunk = blockIdx.x;
    const int row0 = chunk * 64;

    auto load_B = [&](int kt, int st) {
        const __half* Bb = Bw + (size_t)(kt * 16) * 256;
        __half* bs = Bs + st * B2_ST;
#pragma unroll
        for (int i = 0; i < 2; i++) {            // 16 rows x 32 chunks of 8
            int c = tid + i * 256;
            int row = c >> 5, sg = c & 31;
            asm volatile("cp.async.cg.shared.global [%0], [%1], 16;" ::
                         "r"(smem_u32(bs + row * B2ROW + sg * 8)),
                         "l"(Bb + (size_t)row * 256 + sg * 8));
        }
        asm volatile("cp.async.commit_group;");
    };

    // issue first B stages, then run the scan while they fly
    load_B(0, 0);
    load_B(1, 1);
    load_B(2, 2);

    {   // scan prologue: 64 steps, 2 channels per thread
        int n = tid * 2;
        float2 h2 = *(const float2*)(g_H + chunk * kN + n);
#pragma unroll 4
        for (int t = 0; t < 64; t++) {
            size_t o = (size_t)(row0 + t) * kN + n;
            float4 au = *(const float4*)(g_au + o);       // (a0,u0,a1,u1)
            float2 c2 = __half22float2(*(const __half2*)(g_ch + o));
            h2.x = fmaf(au.x, h2.x, au.y);
            h2.y = fmaf(au.z, h2.y, au.w);
            *(__half2*)(As + t * AROWE + n) =
                __floats2half2_rn(c2.x * h2.x, c2.y * h2.y);
        }
    }
    __syncthreads();                              // A operand ready

    float acc[4][4][4];
#pragma unroll
    for (int i = 0; i < 4; i++)
#pragma unroll
        for (int j = 0; j < 4; j++)
#pragma unroll
            for (int q = 0; q < 4; q++) acc[i][j][q] = 0.f;

#pragma unroll 1
    for (int kt = 0; kt < KT; kt++) {
        int s = kt & 3;
        if (kt + 2 < KT)      asm volatile("cp.async.wait_group 2;");
        else if (kt + 1 < KT) asm volatile("cp.async.wait_group 1;");
        else                  asm volatile("cp.async.wait_group 0;");
        __syncthreads();
        if (kt + 3 < KT) load_B(kt + 3, (kt + 3) & 3);

        int aoff = kt * 16;
        __half* bs = Bs + s * B2_ST;
        uint32_t af[4][4];
        uint32_t bf[4][2];
#pragma unroll
        for (int mf = 0; mf < 4; mf++) {
            uint32_t addr = smem_u32(
                As + (mf * 16 + (lane & 15)) * AROWE + aoff + (lane >> 4) * 8);
            asm volatile(
                "ldmatrix.sync.aligned.m8n8.x4.shared.b16 {%0,%1,%2,%3}, [%4];\n"
                : "=r"(af[mf][0]), "=r"(af[mf][1]), "=r"(af[mf][2]), "=r"(af[mf][3])
                : "r"(addr));
        }
#pragma unroll
        for (int p = 0; p < 2; p++) {
            uint32_t addr = smem_u32(
                bs + (lane & 15) * B2ROW + wn + p * 16 + (lane >> 4) * 8);
            uint32_t r0, r1, r2, r3;
            asm volatile(
                "ldmatrix.sync.aligned.m8n8.x4.trans.shared.b16 {%0,%1,%2,%3}, [%4];\n"
                : "=r"(r0), "=r"(r1), "=r"(r2), "=r"(r3)
                : "r"(addr));
            bf[p * 2][0] = r0;     bf[p * 2][1] = r1;
            bf[p * 2 + 1][0] = r2; bf[p * 2 + 1][1] = r3;
        }
#pragma unroll
        for (int mf = 0; mf < 4; mf++) {
#pragma unroll
            for (int nf = 0; nf < 4; nf++) {
                asm volatile(
                    "mma.sync.aligned.m16n8k16.row.col.f32.f16.f16.f32 "
                    "{%0,%1,%2,%3}, {%4,%5,%6,%7}, {%8,%9}, {%0,%1,%2,%3};\n"
                    : "+f"(acc[mf][nf][0]), "+f"(acc[mf][nf][1]),
                      "+f"(acc[mf][nf][2]), "+f"(acc[mf][nf][3])
                    : "r"(af[mf][0]), "r"(af[mf][1]), "r"(af[mf][2]), "r"(af[mf][3]),
                      "r"(bf[nf][0]), "r"(bf[nf][1]));
            }
        }
    }

#pragma unroll
    for (int mf = 0; mf < 4; mf++) {
#pragma unroll
        for (int nf = 0; nf < 4; nf++) {
            int row = row0 + mf * 16 + (lane >> 2);
            int col = wn + nf * 8 + (lane & 3) * 2;
            float b0 = bias[col], b1 = bias[col + 1];
            *reinterpret_cast<float2*>(Cout_ + (size_t)row * kCout + col) =
                make_float2(acc[mf][nf][0] + b0, acc[mf][nf][1] + b1);
            *reinterpret_cast<float2*>(Cout_ + (size_t)(row + 8) * kCout + col) =
                make_float2(acc[mf][nf][2] + b0, acc[mf][nf][3] + b1);
        }
    }
}

// --------------------------------- launcher ---------------------------------
extern "C" void kernel_launch(void* const* d_in, const int* in_sizes, int n_in,
                              void* d_out, int out_size) {
    const float* x   = (const float*)d_in[0];
    const float* Wx  = (const float*)d_in[1];
    const float* bx  = (const float*)d_in[2];
    const float* Wbc = (const float*)d_in[3];
    const float* bbc = (const float*)d_in[4];
    const float* Wd  = (const float*)d_in[5];
    const float* bd  = (const float*)d_in[6];
    const float* Wy  = (const float*)d_in[7];
    const float* by  = (const float*)d_in[8];
    float* out = (float*)d_out;
    (void)in_sizes; (void)n_in; (void)out_size;

    void *p_xp, *p_wp1, *p_wyp;
    cudaGetSymbolAddress(&p_xp,  g_xp);
    cudaGetSymbolAddress(&p_wp1, g_Wp1);
    cudaGetSymbolAddress(&p_wyp, g_Wyp);

    cudaFuncSetAttribute(gemm1_fused, cudaFuncAttributeMaxDynamicSharedMemorySize, GEMM1_SMEM);
    cudaFuncSetAttribute(gemm2f,      cudaFuncAttributeMaxDynamicSharedMemorySize, GEMM2_SMEM);

    pack_x_kernel <<<(kBL * 64) / 256, 256>>>(x);
    pack_w1_kernel<<<(256 * 2048) / 256, 256>>>(Wx, Wbc, Wd);
    pack_wy_kernel<<<(512 * 256) / 256, 256>>>(Wy);

    gemm1_fused<<<dim3(16, 128), 256, GEMM1_SMEM>>>(
        (const __half*)p_xp, (const __half*)p_wp1, bx, bbc, bd);

    scan_phase2<<<8, 256>>>();

    gemm2f<<<kNCHUNK, 256, GEMM2_SMEM>>>(
        (const __half*)p_wyp, by, out);
}

// round 14
// speedup vs baseline: 1.2303x; 1.0871x over previous
#include <cuda_runtime.h>
#include <cuda_fp16.h>
#include <cstdint>

// ---------------------------------------------------------------------------
// S6 block, legacy mma.sync path (tcgen05 unavailable on this build).
// Single-term fp16 GEMMs (m16n8k16.f32.f16.f16.f32 — the only full-rate mma
// on this pipe; fp8 k32=2x cycles, int8 k32=4x, measured R7/R10).
// Intermediate state packed to 8 B/elem: float2( a_fp32, half2(u, c) ).
// gemm1: fp16, fused S6 elementwise + per-64-row-chunk scan aggregates.
// scan2: chunk prefix (8-deep prefetch). gemm2f: per-chunk CTA scans in its
// prologue, holds the fp16 y operand in resident smem (2 CTAs/SM), streams Wy.
// Shapes fixed: B=4, L=4096, Cin=256, N=512, Cout=256.
// ---------------------------------------------------------------------------

constexpr int kBL = 16384, kN = 512, kCout = 256, kL = 4096, kB = 4;
constexpr int kCH = 64;                          // rows per chunk
constexpr int kNCHUNK = kBL / kCH;               // 256 chunks

// ------------------------- scratch (device globals) ------------------------
__device__ __half g_xp [(size_t)kBL * 256];      // fp16 x, [row][256]
__device__ __half g_Wp1[(size_t)256 * 2048];     // fp16 W1, [k][jperm]
__device__ __half g_Wyp[(size_t)512 * 256];      // fp16 Wy, [k][j]
__device__ float2 g_auc[(size_t)kBL * kN];       // (a fp32, half2(u,c))
__device__ float2 g_AB[kNCHUNK * kN];            // per-chunk (A~, B~)
__device__ float  g_H [kNCHUNK * kN];            // chunk-start h

__device__ __forceinline__ uint32_t smem_u32(const void* p) {
    return (uint32_t)__cvta_generic_to_shared(p);
}

// ------------------------------ pack kernels --------------------------------
__global__ void pack_x_kernel(const float* __restrict__ x) {
    int idx = blockIdx.x * 256 + threadIdx.x;            // kBL*64 total
    int row = idx >> 6, k4 = (idx & 63) << 2;
    float4 v = *(const float4*)(x + (size_t)row * 256 + k4);
    __half2 h01 = __floats2half2_rn(v.x, v.y);
    __half2 h23 = __floats2half2_rn(v.z, v.w);
    __half2* ph = (__half2*)(g_xp + (size_t)row * 256 + k4);
    ph[0] = h01;
    ph[1] = h23;
}

// Permuted W1 columns. For j = n128*128 + w*32 + nf*8 + q2*2 + r:
//   group g = n128*32 + w*8 + (nf>>1)*4 + q2,  member m = (nf&1)*2 + r
//   m: 0=Wx[:,g] 1=Wbc[:,g] 2=Wbc[:,512+g] 3=Wd[:,g]
__global__ void pack_w1_kernel(const float* __restrict__ Wx,
                               const float* __restrict__ Wbc,
                               const float* __restrict__ Wd) {
    int idx = blockIdx.x * 256 + threadIdx.x;            // 256*2048 total
    int k = idx >> 11, j = idx & 2047;
    int g = (j >> 7) * 32 + ((j >> 5) & 3) * 8 + ((j >> 4) & 1) * 4 + ((j >> 1) & 3);
    int m = ((j >> 3) & 1) * 2 + (j & 1);
    float w;
    if (m == 0)      w = Wx [k * 512  + g];
    else if (m == 1) w = Wbc[k * 1024 + g];
    else if (m == 2) w = Wbc[k * 1024 + 512 + g];
    else             w = Wd [k * 512  + g];
    g_Wp1[(size_t)k * 2048 + j] = __float2half_rn(w);
}

__global__ void pack_wy_kernel(const float* __restrict__ Wy) {
    int idx = blockIdx.x * 256 + threadIdx.x;            // 512*256 total
    g_Wyp[idx] = __float2half_rn(Wy[idx]);
}

// ----------------------------- gemm1 (fp16) ---------------------------------
// CTA 128x128 out, 8 warps of 64x32, k-tile 32 elems, 4-stage cp.async.
#define STAGES 4
constexpr int A_STB = 128 * 80;                  // 128 rows x (64B + 16 pad)
constexpr int B_STB = 32 * 272;                  // 32 k-rows x (256B + 16 pad)
constexpr int GEMM1_SMEM = STAGES * (A_STB + B_STB);      // 75776

__global__ void __launch_bounds__(256, 2)
gemm1_fused(const __half* __restrict__ AH,       // [row][256]
            const __half* __restrict__ BH,       // [k][2048]
            const float* __restrict__ bx, const float* __restrict__ bbc,
            const float* __restrict__ bd) {
    extern __shared__ __align__(16) char smc[];
    char* As = smc;
    char* Bs = smc + STAGES * A_STB;

    constexpr int KT = 8;                        // 256 / 32
    constexpr int ASTR = 512;                    // bytes per A row
    constexpr int BSTR = 4096;                   // bytes per B k-row

    const int tid = threadIdx.x, lane = tid & 31, warp = tid >> 5;
    const int wm = (warp >> 2) * 64, wn = (warp & 3) * 32;
    const int bm = blockIdx.y * 128, bn = blockIdx.x * 128;

    float acc[4][4][4];
#pragma unroll
    for (int i = 0; i < 4; i++)
#pragma unroll
        for (int j = 0; j < 4; j++)
#pragma unroll
            for (int q = 0; q < 4; q++) acc[i][j][q] = 0.f;

    auto load_tile = [&](int kt, int st) {
        const char* Ab = (const char*)AH + kt * 64;
        const char* Bb = (const char*)BH + (size_t)(kt * 32) * BSTR;
        char* as = As + st * A_STB;
#pragma unroll
        for (int i = 0; i < 2; i++) {            // A: 128 rows x 4 x16B
            int c = tid + i * 256;
            int row = c >> 2, sg = c & 3;
            asm volatile("cp.async.cg.shared.global [%0], [%1], 16;" ::
                         "r"(smem_u32(as + row * 80 + sg * 16)),
                         "l"(Ab + (size_t)(bm + row) * ASTR + sg * 16));
        }
        char* bs = Bs + st * B_STB;
#pragma unroll
        for (int i = 0; i < 2; i++) {            // B: 32 rows x 16 x16B
            int c = tid + i * 256;
            int row = c >> 4, sg = c & 15;
            asm volatile("cp.async.cg.shared.global [%0], [%1], 16;" ::
                         "r"(smem_u32(bs + row * 272 + sg * 16)),
                         "l"(Bb + (size_t)row * BSTR + bn * 2 + sg * 16));
        }
        asm volatile("cp.async.commit_group;");
    };

    load_tile(0, 0);
    load_tile(1, 1);
    load_tile(2, 2);

#pragma unroll 1
    for (int kt = 0; kt < KT; kt++) {
        int s = kt & 3;
        if (kt + 2 < KT)      asm volatile("cp.async.wait_group 2;");
        else if (kt + 1 < KT) asm volatile("cp.async.wait_group 1;");
        else                  asm volatile("cp.async.wait_group 0;");
        __syncthreads();
        if (kt + 3 < KT) load_tile(kt + 3, (kt + 3) & 3);

        char* as = As + s * A_STB;
        char* bs = Bs + s * B_STB;
#pragma unroll
        for (int ks = 0; ks < 2; ks++) {
            uint32_t af[4][4];
            uint32_t bf[4][2];
#pragma unroll
            for (int mf = 0; mf < 4; mf++) {
                uint32_t addr = smem_u32(
                    as + (wm + mf * 16 + (lane & 15)) * 80 + ks * 32 + (lane >> 4) * 16);
                asm volatile(
                    "ldmatrix.sync.aligned.m8n8.x4.shared.b16 {%0,%1,%2,%3}, [%4];\n"
                    : "=r"(af[mf][0]), "=r"(af[mf][1]), "=r"(af[mf][2]), "=r"(af[mf][3])
                    : "r"(addr));
            }
#pragma unroll
            for (int p = 0; p < 2; p++) {
                uint32_t addr = smem_u32(
                    bs + (ks * 16 + (lane & 15)) * 272 + (wn + p * 16 + (lane >> 4) * 8) * 2);
                uint32_t r0, r1, r2, r3;
                asm volatile(
                    "ldmatrix.sync.aligned.m8n8.x4.trans.shared.b16 {%0,%1,%2,%3}, [%4];\n"
                    : "=r"(r0), "=r"(r1), "=r"(r2), "=r"(r3)
                    : "r"(addr));
                bf[p * 2][0] = r0;     bf[p * 2][1] = r1;
                bf[p * 2 + 1][0] = r2; bf[p * 2 + 1][1] = r3;
            }
#pragma unroll
            for (int mf = 0; mf < 4; mf++) {
#pragma unroll
                for (int nf = 0; nf < 4; nf++) {
                    asm volatile(
                        "mma.sync.aligned.m16n8k16.row.col.f32.f16.f16.f32 "
                        "{%0,%1,%2,%3}, {%4,%5,%6,%7}, {%8,%9}, {%0,%1,%2,%3};\n"
                        : "+f"(acc[mf][nf][0]), "+f"(acc[mf][nf][1]),
                          "+f"(acc[mf][nf][2]), "+f"(acc[mf][nf][3])
                        : "r"(af[mf][0]), "r"(af[mf][1]), "r"(af[mf][2]), "r"(af[mf][3]),
                          "r"(bf[nf][0]), "r"(bf[nf][1]));
                }
            }
        }
    }

    // Fused S6 elementwise + per-64-row-chunk scan aggregates.
    // Warp-row (warps 0-3 -> rows 0..63, warps 4-7 -> 64..127) == one chunk.
    const int gbase = (bn >> 2) + (wn >> 2) + (lane & 3);
    const int chunk = blockIdx.y * 2 + (warp >> 2);
#pragma unroll
    for (int t2 = 0; t2 < 2; t2++) {
        int g = gbase + t2 * 4;
        float vbx = bx[g], vbb = bbc[g], vbc = bbc[512 + g], vbd = bd[g];
        float At = 1.f, Bt = 0.f;
#pragma unroll
        for (int mf = 0; mf < 4; mf++) {
#pragma unroll
            for (int h = 0; h < 2; h++) {
                int R = bm + wm + mf * 16 + h * 8 + (lane >> 2);
                float xv = acc[mf][2 * t2 + 0][h * 2 + 0] + vbx;
                float bv = acc[mf][2 * t2 + 0][h * 2 + 1] + vbb;
                float cc = acc[mf][2 * t2 + 1][h * 2 + 0] + vbc;
                float dd = acc[mf][2 * t2 + 1][h * 2 + 1] + vbd;
                float Aa = 1.0f / (1.0f + expf(dd));
                float uu = (1.0f - Aa) * bv * xv;
                size_t o = (size_t)R * kN + g;
                __half2 uc = __halves2half2(__float2half_rn(uu), __float2half_rn(cc));
                g_auc[o] = make_float2(Aa, __uint_as_float(*(uint32_t*)&uc));
                float A1 = Aa, B1 = uu;
#pragma unroll
                for (int st = 4; st <= 16; st <<= 1) {
                    float pa = __shfl_xor_sync(0xffffffffu, A1, st);
                    float pb = __shfl_xor_sync(0xffffffffu, B1, st);
                    if ((lane & st) == 0) {
                        B1 = pa * B1 + pb;
                        A1 = A1 * pa;
                    } else {
                        B1 = A1 * pb + B1;
                        A1 = pa * A1;
                    }
                }
                Bt = A1 * Bt + B1;
                At = At * A1;
            }
        }
        if ((lane >> 2) == 0) g_AB[chunk * kN + g] = make_float2(At, Bt);
    }
}

// ------------------------------- chunk prefix -------------------------------
__global__ void scan_phase2() {
    int b = blockIdx.x >> 1;
    int n = (blockIdx.x & 1) * 256 + threadIdx.x;
    int base = b * 64;
    float2 buf[8];
#pragma unroll
    for (int i = 0; i < 8; i++) buf[i] = g_AB[(base + i) * kN + n];
    float h = 0.f;
#pragma unroll 8
    for (int ch = 0; ch < 64; ch++) {
        float2 cur = buf[ch & 7];
        if (ch + 8 < 64) buf[ch & 7] = g_AB[(base + ch + 8) * kN + n];
        g_H[(base + ch) * kN + n] = h;
        h = fmaf(cur.x, h, cur.y);
    }
}

// ------------------- gemm2f: fused scan + output GEMM -----------------------
// One CTA per 64-row chunk. Prologue: scan 64 steps, write fp16 y operand
// into resident smem (66.5KB). Mainloop: single-term fp16, A resident,
// Wy streamed via 4-stage 16-k-row tiles -> 100KB total, 2 CTAs/SM.
constexpr int AROWE = 520;                       // 512 elems + 8 pad
constexpr int A2_BYTES = 64 * AROWE * 2;         // 66560
constexpr int B2ROW = 264;
constexpr int B2_ST = 16 * B2ROW;                // elems per stage (4224)
constexpr int GEMM2_SMEM = A2_BYTES + STAGES * B2_ST * 2;   // 100352

__global__ void __launch_bounds__(256, 2)
gemm2f(const __half* __restrict__ Bw,            // g_Wyp [512][256]
       const float* __restrict__ bias,
       float* __restrict__ Cout_) {
    extern __shared__ __align__(16) char smc[];
    __half* As = (__half*)smc;
    __half* Bs = (__half*)(smc + A2_BYTES);

    constexpr int KT = 32;                       // 512 / 16
    const int tid = threadIdx.x, lane = tid & 31, warp = tid >> 5;
    const int wn = warp * 32;
    const int chunk = blockIdx.x;
    const int row0 = chunk * 64;

    auto load_B = [&](int kt, int st) {
        const __half* Bb = Bw + (size_t)(kt * 16) * 256;
        __half* bs = Bs + st * B2_ST;
#pragma unroll
        for (int i = 0; i < 2; i++) {            // 16 rows x 32 chunks of 8
            int c = tid + i * 256;
            int row = c >> 5, sg = c & 31;
            asm volatile("cp.async.cg.shared.global [%0], [%1], 16;" ::
                         "r"(smem_u32(bs + row * B2ROW + sg * 8)),
                         "l"(Bb + (size_t)row * 256 + sg * 8));
        }
        asm volatile("cp.async.commit_group;");
    };

    // issue first B stages, then run the scan while they fly
    load_B(0, 0);
    load_B(1, 1);
    load_B(2, 2);

    {   // scan prologue: 64 steps, 2 channels per thread
        int n = tid * 2;
        float2 h2 = *(const float2*)(g_H + chunk * kN + n);
#pragma unroll 4
        for (int t = 0; t < 64; t++) {
            size_t o = (size_t)(row0 + t) * kN + n;
            float4 v = *(const float4*)(g_auc + o);       // (a0, uc0, a1, uc1)
            uint32_t w0 = __float_as_uint(v.y);
            uint32_t w1 = __float_as_uint(v.w);
            float2 uc0 = __half22float2(*(__half2*)&w0);
            float2 uc1 = __half22float2(*(__half2*)&w1);
            h2.x = fmaf(v.x, h2.x, uc0.x);
            h2.y = fmaf(v.z, h2.y, uc1.x);
            *(__half2*)(As + t * AROWE + n) =
                __floats2half2_rn(uc0.y * h2.x, uc1.y * h2.y);
        }
    }
    __syncthreads();                              // A operand ready

    float acc[4][4][4];
#pragma unroll
    for (int i = 0; i < 4; i++)
#pragma unroll
        for (int j = 0; j < 4; j++)
#pragma unroll
            for (int q = 0; q < 4; q++) acc[i][j][q] = 0.f;

#pragma unroll 1
    for (int kt = 0; kt < KT; kt++) {
        int s = kt & 3;
        if (kt + 2 < KT)      asm volatile("cp.async.wait_group 2;");
        else if (kt + 1 < KT) asm volatile("cp.async.wait_group 1;");
        else                  asm volatile("cp.async.wait_group 0;");
        __syncthreads();
        if (kt + 3 < KT) load_B(kt + 3, (kt + 3) & 3);

        int aoff = kt * 16;
        __half* bs = Bs + s * B2_ST;
        uint32_t af[4][4];
        uint32_t bf[4][2];
#pragma unroll
        for (int mf = 0; mf < 4; mf++) {
            uint32_t addr = smem_u32(
                As + (mf * 16 + (lane & 15)) * AROWE + aoff + (lane >> 4) * 8);
            asm volatile(
                "ldmatrix.sync.aligned.m8n8.x4.shared.b16 {%0,%1,%2,%3}, [%4];\n"
                : "=r"(af[mf][0]), "=r"(af[mf][1]), "=r"(af[mf][2]), "=r"(af[mf][3])
                : "r"(addr));
        }
#pragma unroll
        for (int p = 0; p < 2; p++) {
            uint32_t addr = smem_u32(
                bs + (lane & 15) * B2ROW + wn + p * 16 + (lane >> 4) * 8);
            uint32_t r0, r1, r2, r3;
            asm volatile(
                "ldmatrix.sync.aligned.m8n8.x4.trans.shared.b16 {%0,%1,%2,%3}, [%4];\n"
                : "=r"(r0), "=r"(r1), "=r"(r2), "=r"(r3)
                : "r"(addr));
            bf[p * 2][0] = r0;     bf[p * 2][1] = r1;
            bf[p * 2 + 1][0] = r2; bf[p * 2 + 1][1] = r3;
        }
#pragma unroll
        for (int mf = 0; mf < 4; mf++) {
#pragma unroll
            for (int nf = 0; nf < 4; nf++) {
                asm volatile(
                    "mma.sync.aligned.m16n8k16.row.col.f32.f16.f16.f32 "
                    "{%0,%1,%2,%3}, {%4,%5,%6,%7}, {%8,%9}, {%0,%1,%2,%3};\n"
                    : "+f"(acc[mf][nf][0]), "+f"(acc[mf][nf][1]),
                      "+f"(acc[mf][nf][2]), "+f"(acc[mf][nf][3])
                    : "r"(af[mf][0]), "r"(af[mf][1]), "r"(af[mf][2]), "r"(af[mf][3]),
                      "r"(bf[nf][0]), "r"(bf[nf][1]));
            }
        }
    }

#pragma unroll
    for (int mf = 0; mf < 4; mf++) {
#pragma unroll
        for (int nf = 0; nf < 4; nf++) {
            int row = row0 + mf * 16 + (lane >> 2);
            int col = wn + nf * 8 + (lane & 3) * 2;
            float b0 = bias[col], b1 = bias[col + 1];
            *reinterpret_cast<float2*>(Cout_ + (size_t)row * kCout + col) =
                make_float2(acc[mf][nf][0] + b0, acc[mf][nf][1] + b1);
            *reinterpret_cast<float2*>(Cout_ + (size_t)(row + 8) * kCout + col) =
                make_float2(acc[mf][nf][2] + b0, acc[mf][nf][3] + b1);
        }
    }
}

// --------------------------------- launcher ---------------------------------
extern "C" void kernel_launch(void* const* d_in, const int* in_sizes, int n_in,
                              void* d_out, int out_size) {
    const float* x   = (const float*)d_in[0];
    const float* Wx  = (const float*)d_in[1];
    const float* bx  = (const float*)d_in[2];
    const float* Wbc = (const float*)d_in[3];
    const float* bbc = (const float*)d_in[4];
    const float* Wd  = (const float*)d_in[5];
    const float* bd  = (const float*)d_in[6];
    const float* Wy  = (const float*)d_in[7];
    const float* by  = (const float*)d_in[8];
    float* out = (float*)d_out;
    (void)in_sizes; (void)n_in; (void)out_size;

    void *p_xp, *p_wp1, *p_wyp;
    cudaGetSymbolAddress(&p_xp,  g_xp);
    cudaGetSymbolAddress(&p_wp1, g_Wp1);
    cudaGetSymbolAddress(&p_wyp, g_Wyp);

    cudaFuncSetAttribute(gemm1_fused, cudaFuncAttributeMaxDynamicSharedMemorySize, GEMM1_SMEM);
    cudaFuncSetAttribute(gemm2f,      cudaFuncAttributeMaxDynamicSharedMemorySize, GEMM2_SMEM);

    pack_x_kernel <<<(kBL * 64) / 256, 256>>>(x);
    pack_w1_kernel<<<(256 * 2048) / 256, 256>>>(Wx, Wbc, Wd);
    pack_wy_kernel<<<(512 * 256) / 256, 256>>>(Wy);

    gemm1_fused<<<dim3(16, 128), 256, GEMM1_SMEM>>>(
        (const __half*)p_xp, (const __half*)p_wp1, bx, bbc, bd);

    scan_phase2<<<8, 256>>>();

    gemm2f<<<kNCHUNK, 256, GEMM2_SMEM>>>(
        (const __half*)p_wyp, by, out);
}

// round 15
// speedup vs baseline: 1.2724x; 1.0342x over previous
#include <cuda_runtime.h>
#include <cuda_fp16.h>
#include <cstdint>

// ---------------------------------------------------------------------------
// S6 block, legacy mma.sync path (tcgen05 unavailable on this build).
// Single-term fp16 GEMMs (m16n8k16.f32.f16.f16.f32 — the only full-rate mma
// on this pipe; fp8 k32=2x cycles, int8 k32=4x, measured R7/R10).
// Intermediate state packed to 8 B/elem: float2( a_fp32, half2(u, c) ).
// gemm1: fp16, member-major W permutation -> each thread owns 2 ADJACENT
//        groups -> float4 epilogue stores; fast-sigmoid (__expf/__fdividef);
//        fused per-64-row-chunk scan aggregates.
// scan2: chunk prefix (8-deep prefetch). gemm2f: per-chunk CTA scans in its
// prologue, holds the fp16 y operand in resident smem (2 CTAs/SM), streams Wy.
// Shapes fixed: B=4, L=4096, Cin=256, N=512, Cout=256.
// ---------------------------------------------------------------------------

constexpr int kBL = 16384, kN = 512, kCout = 256, kL = 4096, kB = 4;
constexpr int kCH = 64;                          // rows per chunk
constexpr int kNCHUNK = kBL / kCH;               // 256 chunks

// ------------------------- scratch (device globals) ------------------------
__device__ __half g_xp [(size_t)kBL * 256];      // fp16 x, [row][256]
__device__ __half g_Wp1[(size_t)256 * 2048];     // fp16 W1, [k][jperm]
__device__ __half g_Wyp[(size_t)512 * 256];      // fp16 Wy, [k][j]
__device__ float2 g_auc[(size_t)kBL * kN];       // (a fp32, half2(u,c))
__device__ float2 g_AB[kNCHUNK * kN];            // per-chunk (A~, B~)
__device__ float  g_H [kNCHUNK * kN];            // chunk-start h

__device__ __forceinline__ uint32_t smem_u32(const void* p) {
    return (uint32_t)__cvta_generic_to_shared(p);
}

// ------------------------------ pack kernels --------------------------------
__global__ void pack_x_kernel(const float* __restrict__ x) {
    int idx = blockIdx.x * 256 + threadIdx.x;            // kBL*64 total
    int row = idx >> 6, k4 = (idx & 63) << 2;
    float4 v = *(const float4*)(x + (size_t)row * 256 + k4);
    __half2 h01 = __floats2half2_rn(v.x, v.y);
    __half2 h23 = __floats2half2_rn(v.z, v.w);
    __half2* ph = (__half2*)(g_xp + (size_t)row * 256 + k4);
    ph[0] = h01;
    ph[1] = h23;
}

// Member-major permuted W1 columns.
// j = n128*128 + w*32 + m*8 + goff  (n128=j>>7, w=(j>>5)&3, m=(j>>3)&3, goff=j&7)
// group g = n128*32 + w*8 + goff;  m: 0=Wx[:,g] 1=Wbc[:,g] 2=Wbc[:,512+g] 3=Wd[:,g]
// In the mma fragment, thread q=lane&3 then owns groups 2q and 2q+1 fully.
__global__ void pack_w1_kernel(const float* __restrict__ Wx,
                               const float* __restrict__ Wbc,
                               const float* __restrict__ Wd) {
    int idx = blockIdx.x * 256 + threadIdx.x;            // 256*2048 total
    int k = idx >> 11, j = idx & 2047;
    int g = (j >> 7) * 32 + ((j >> 5) & 3) * 8 + (j & 7);
    int m = (j >> 3) & 3;
    float w;
    if (m == 0)      w = Wx [k * 512  + g];
    else if (m == 1) w = Wbc[k * 1024 + g];
    else if (m == 2) w = Wbc[k * 1024 + 512 + g];
    else             w = Wd [k * 512  + g];
    g_Wp1[(size_t)k * 2048 + j] = __float2half_rn(w);
}

__global__ void pack_wy_kernel(const float* __restrict__ Wy) {
    int idx = blockIdx.x * 256 + threadIdx.x;            // 512*256 total
    g_Wyp[idx] = __float2half_rn(Wy[idx]);
}

// ----------------------------- gemm1 (fp16) ---------------------------------
// CTA 128x128 out, 8 warps of 64x32, k-tile 32 elems, 4-stage cp.async.
#define STAGES 4
constexpr int A_STB = 128 * 80;                  // 128 rows x (64B + 16 pad)
constexpr int B_STB = 32 * 272;                  // 32 k-rows x (256B + 16 pad)
constexpr int GEMM1_SMEM = STAGES * (A_STB + B_STB);      // 75776

__global__ void __launch_bounds__(256, 2)
gemm1_fused(const __half* __restrict__ AH,       // [row][256]
            const __half* __restrict__ BH,       // [k][2048]
            const float* __restrict__ bx, const float* __restrict__ bbc,
            const float* __restrict__ bd) {
    extern __shared__ __align__(16) char smc[];
    char* As = smc;
    char* Bs = smc + STAGES * A_STB;

    constexpr int KT = 8;                        // 256 / 32
    constexpr int ASTR = 512;                    // bytes per A row
    constexpr int BSTR = 4096;                   // bytes per B k-row

    const int tid = threadIdx.x, lane = tid & 31, warp = tid >> 5;
    const int wm = (warp >> 2) * 64, wn = (warp & 3) * 32;
    const int bm = blockIdx.y * 128, bn = blockIdx.x * 128;

    float acc[4][4][4];
#pragma unroll
    for (int i = 0; i < 4; i++)
#pragma unroll
        for (int j = 0; j < 4; j++)
#pragma unroll
            for (int q = 0; q < 4; q++) acc[i][j][q] = 0.f;

    auto load_tile = [&](int kt, int st) {
        const char* Ab = (const char*)AH + kt * 64;
        const char* Bb = (const char*)BH + (size_t)(kt * 32) * BSTR;
        char* as = As + st * A_STB;
#pragma unroll
        for (int i = 0; i < 2; i++) {            // A: 128 rows x 4 x16B
            int c = tid + i * 256;
            int row = c >> 2, sg = c & 3;
            asm volatile("cp.async.cg.shared.global [%0], [%1], 16;" ::
                         "r"(smem_u32(as + row * 80 + sg * 16)),
                         "l"(Ab + (size_t)(bm + row) * ASTR + sg * 16));
        }
        char* bs = Bs + st * B_STB;
#pragma unroll
        for (int i = 0; i < 2; i++) {            // B: 32 rows x 16 x16B
            int c = tid + i * 256;
            int row = c >> 4, sg = c & 15;
            asm volatile("cp.async.cg.shared.global [%0], [%1], 16;" ::
                         "r"(smem_u32(bs + row * 272 + sg * 16)),
                         "l"(Bb + (size_t)row * BSTR + bn * 2 + sg * 16));
        }
        asm volatile("cp.async.commit_group;");
    };

    load_tile(0, 0);
    load_tile(1, 1);
    load_tile(2, 2);

#pragma unroll 1
    for (int kt = 0; kt < KT; kt++) {
        int s = kt & 3;
        if (kt + 2 < KT)      asm volatile("cp.async.wait_group 2;");
        else if (kt + 1 < KT) asm volatile("cp.async.wait_group 1;");
        else                  asm volatile("cp.async.wait_group 0;");
        __syncthreads();
        if (kt + 3 < KT) load_tile(kt + 3, (kt + 3) & 3);

        char* as = As + s * A_STB;
        char* bs = Bs + s * B_STB;
#pragma unroll
        for (int ks = 0; ks < 2; ks++) {
            uint32_t af[4][4];
            uint32_t bf[4][2];
#pragma unroll
            for (int mf = 0; mf < 4; mf++) {
                uint32_t addr = smem_u32(
                    as + (wm + mf * 16 + (lane & 15)) * 80 + ks * 32 + (lane >> 4) * 16);
                asm volatile(
                    "ldmatrix.sync.aligned.m8n8.x4.shared.b16 {%0,%1,%2,%3}, [%4];\n"
                    : "=r"(af[mf][0]), "=r"(af[mf][1]), "=r"(af[mf][2]), "=r"(af[mf][3])
                    : "r"(addr));
            }
#pragma unroll
            for (int p = 0; p < 2; p++) {
                uint32_t addr = smem_u32(
                    bs + (ks * 16 + (lane & 15)) * 272 + (wn + p * 16 + (lane >> 4) * 8) * 2);
                uint32_t r0, r1, r2, r3;
                asm volatile(
                    "ldmatrix.sync.aligned.m8n8.x4.trans.shared.b16 {%0,%1,%2,%3}, [%4];\n"
                    : "=r"(r0), "=r"(r1), "=r"(r2), "=r"(r3)
                    : "r"(addr));
                bf[p * 2][0] = r0;     bf[p * 2][1] = r1;
                bf[p * 2 + 1][0] = r2; bf[p * 2 + 1][1] = r3;
            }
#pragma unroll
            for (int mf = 0; mf < 4; mf++) {
#pragma unroll
                for (int nf = 0; nf < 4; nf++) {
                    asm volatile(
                        "mma.sync.aligned.m16n8k16.row.col.f32.f16.f16.f32 "
                        "{%0,%1,%2,%3}, {%4,%5,%6,%7}, {%8,%9}, {%0,%1,%2,%3};\n"
                        : "+f"(acc[mf][nf][0]), "+f"(acc[mf][nf][1]),
                          "+f"(acc[mf][nf][2]), "+f"(acc[mf][nf][3])
                        : "r"(af[mf][0]), "r"(af[mf][1]), "r"(af[mf][2]), "r"(af[mf][3]),
                          "r"(bf[nf][0]), "r"(bf[nf][1]));
                }
            }
        }
    }

    // Fused S6 elementwise + per-64-row-chunk scan aggregates.
    // Member-major layout: acc[mf][m][h*2+gg] = member m of group g0+gg.
    // Each thread owns the two ADJACENT groups g0, g0+1 -> one float4 store.
    const int g0 = (bn >> 2) + (wn >> 2) + (lane & 3) * 2;
    const int chunk = blockIdx.y * 2 + (warp >> 2);
    float vbx0 = bx[g0],        vbx1 = bx[g0 + 1];
    float vbb0 = bbc[g0],       vbb1 = bbc[g0 + 1];
    float vbc0 = bbc[512 + g0], vbc1 = bbc[512 + g0 + 1];
    float vbd0 = bd[g0],        vbd1 = bd[g0 + 1];
    float At0 = 1.f, Bt0 = 0.f, At1 = 1.f, Bt1 = 0.f;
#pragma unroll
    for (int mf = 0; mf < 4; mf++) {
#pragma unroll
        for (int h = 0; h < 2; h++) {
            int R = bm + wm + mf * 16 + h * 8 + (lane >> 2);
            float xv0 = acc[mf][0][h * 2 + 0] + vbx0;
            float bv0 = acc[mf][1][h * 2 + 0] + vbb0;
            float cc0 = acc[mf][2][h * 2 + 0] + vbc0;
            float dd0 = acc[mf][3][h * 2 + 0] + vbd0;
            float xv1 = acc[mf][0][h * 2 + 1] + vbx1;
            float bv1 = acc[mf][1][h * 2 + 1] + vbb1;
            float cc1 = acc[mf][2][h * 2 + 1] + vbc1;
            float dd1 = acc[mf][3][h * 2 + 1] + vbd1;
            float Aa0 = __fdividef(1.0f, 1.0f + __expf(dd0));
            float Aa1 = __fdividef(1.0f, 1.0f + __expf(dd1));
            float uu0 = (1.0f - Aa0) * bv0 * xv0;
            float uu1 = (1.0f - Aa1) * bv1 * xv1;
            __half2 uc0 = __floats2half2_rn(uu0, cc0);
            __half2 uc1 = __floats2half2_rn(uu1, cc1);
            float4 st;
            st.x = Aa0;
            st.y = __uint_as_float(*(uint32_t*)&uc0);
            st.z = Aa1;
            st.w = __uint_as_float(*(uint32_t*)&uc1);
            *(float4*)(g_auc + (size_t)R * kN + g0) = st;
            // order-aware butterfly over q bits (rows), then sequential
            float A1 = Aa0, B1 = uu0;
            float A2 = Aa1, B2 = uu1;
#pragma unroll
            for (int st2 = 4; st2 <= 16; st2 <<= 1) {
                float pa = __shfl_xor_sync(0xffffffffu, A1, st2);
                float pb = __shfl_xor_sync(0xffffffffu, B1, st2);
                float qa = __shfl_xor_sync(0xffffffffu, A2, st2);
                float qb = __shfl_xor_sync(0xffffffffu, B2, st2);
                if ((lane & st2) == 0) {
                    B1 = pa * B1 + pb;  A1 = A1 * pa;
                    B2 = qa * B2 + qb;  A2 = A2 * qa;
                } else {
                    B1 = A1 * pb + B1;  A1 = pa * A1;
                    B2 = A2 * qb + B2;  A2 = qa * A2;
                }
            }
            Bt0 = A1 * Bt0 + B1;  At0 = At0 * A1;
            Bt1 = A2 * Bt1 + B2;  At1 = At1 * A2;
        }
    }
    if ((lane >> 2) == 0) {
        float4 ab;
        ab.x = At0; ab.y = Bt0; ab.z = At1; ab.w = Bt1;
        *(float4*)(g_AB + chunk * kN + g0) = ab;
    }
}

// ------------------------------- chunk prefix -------------------------------
__global__ void scan_phase2() {
    int b = blockIdx.x >> 1;
    int n = (blockIdx.x & 1) * 256 + threadIdx.x;
    int base = b * 64;
    float2 buf[8];
#pragma unroll
    for (int i = 0; i < 8; i++) buf[i] = g_AB[(base + i) * kN + n];
    float h = 0.f;
#pragma unroll 8
    for (int ch = 0; ch < 64; ch++) {
        float2 cur = buf[ch & 7];
        if (ch + 8 < 64) buf[ch & 7] = g_AB[(base + ch + 8) * kN + n];
        g_H[(base + ch) * kN + n] = h;
        h = fmaf(cur.x, h, cur.y);
    }
}

// ------------------- gemm2f: fused scan + output GEMM -----------------------
// One CTA per 64-row chunk. Prologue: scan 64 steps, write fp16 y operand
// into resident smem (66.5KB). Mainloop: single-term fp16, A resident,
// Wy streamed via 4-stage 16-k-row tiles -> 100KB total, 2 CTAs/SM.
constexpr int AROWE = 520;                       // 512 elems + 8 pad
constexpr int A2_BYTES = 64 * AROWE * 2;         // 66560
constexpr int B2ROW = 264;
constexpr int B2_ST = 16 * B2ROW;                // elems per stage (4224)
constexpr int GEMM2_SMEM = A2_BYTES + STAGES * B2_ST * 2;   // 100352

__global__ void __launch_bounds__(256, 2)
gemm2f(const __half* __restrict__ Bw,            // g_Wyp [512][256]
       const float* __restrict__ bias,
       float* __restrict__ Cout_) {
    extern __shared__ __align__(16) char smc[];
    __half* As = (__half*)smc;
    __half* Bs = (__half*)(smc + A2_BYTES);

    constexpr int KT = 32;                       // 512 / 16
    const int tid = threadIdx.x, lane = tid & 31, warp = tid >> 5;
    const int wn = warp * 32;
    const int chunk = blockIdx.x;
    const int row0 = chunk * 64;

    auto load_B = [&](int kt, int st) {
        const __half* Bb = Bw + (size_t)(kt * 16) * 256;
        __half* bs = Bs + st * B2_ST;
#pragma unroll
        for (int i = 0; i < 2; i++) {            // 16 rows x 32 chunks of 8
            int c = tid + i * 256;
            int row = c >> 5, sg = c & 31;
            asm volatile("cp.async.cg.shared.global [%0], [%1], 16;" ::
                         "r"(smem_u32(bs + row * B2ROW + sg * 8)),
                         "l"(Bb + (size_t)row * 256 + sg * 8));
        }
        asm volatile("cp.async.commit_group;");
    };

    // issue first B stages, then run the scan while they fly
    load_B(0, 0);
    load_B(1, 1);
    load_B(2, 2);

    {   // scan prologue: 64 steps, 2 channels per thread
        int n = tid * 2;
        float2 h2 = *(const float2*)(g_H + chunk * kN + n);
#pragma unroll 4
        for (int t = 0; t < 64; t++) {
            size_t o = (size_t)(row0 + t) * kN + n;
            float4 v = *(const float4*)(g_auc + o);       // (a0, uc0, a1, uc1)
            uint32_t w0 = __float_as_uint(v.y);
            uint32_t w1 = __float_as_uint(v.w);
            float2 uc0 = __half22float2(*(__half2*)&w0);
            float2 uc1 = __half22float2(*(__half2*)&w1);
            h2.x = fmaf(v.x, h2.x, uc0.x);
            h2.y = fmaf(v.z, h2.y, uc1.x);
            *(__half2*)(As + t * AROWE + n) =
                __floats2half2_rn(uc0.y * h2.x, uc1.y * h2.y);
        }
    }
    __syncthreads();                              // A operand ready

    float acc[4][4][4];
#pragma unroll
    for (int i = 0; i < 4; i++)
#pragma unroll
        for (int j = 0; j < 4; j++)
#pragma unroll
            for (int q = 0; q < 4; q++) acc[i][j][q] = 0.f;

#pragma unroll 1
    for (int kt = 0; kt < KT; kt++) {
        int s = kt & 3;
        if (kt + 2 < KT)      asm volatile("cp.async.wait_group 2;");
        else if (kt + 1 < KT) asm volatile("cp.async.wait_group 1;");
        else                  asm volatile("cp.async.wait_group 0;");
        __syncthreads();
        if (kt + 3 < KT) load_B(kt + 3, (kt + 3) & 3);

        int aoff = kt * 16;
        __half* bs = Bs + s * B2_ST;
        uint32_t af[4][4];
        uint32_t bf[4][2];
#pragma unroll
        for (int mf = 0; mf < 4; mf++) {
            uint32_t addr = smem_u32(
                As + (mf * 16 + (lane & 15)) * AROWE + aoff + (lane >> 4) * 8);
            asm volatile(
                "ldmatrix.sync.aligned.m8n8.x4.shared.b16 {%0,%1,%2,%3}, [%4];\n"
                : "=r"(af[mf][0]), "=r"(af[mf][1]), "=r"(af[mf][2]), "=r"(af[mf][3])
                : "r"(addr));
        }
#pragma unroll
        for (int p = 0; p < 2; p++) {
            uint32_t addr = smem_u32(
                bs + (lane & 15) * B2ROW + wn + p * 16 + (lane >> 4) * 8);
            uint32_t r0, r1, r2, r3;
            asm volatile(
                "ldmatrix.sync.aligned.m8n8.x4.trans.shared.b16 {%0,%1,%2,%3}, [%4];\n"
                : "=r"(r0), "=r"(r1), "=r"(r2), "=r"(r3)
                : "r"(addr));
            bf[p * 2][0] = r0;     bf[p * 2][1] = r1;
            bf[p * 2 + 1][0] = r2; bf[p * 2 + 1][1] = r3;
        }
#pragma unroll
        for (int mf = 0; mf < 4; mf++) {
#pragma unroll
            for (int nf = 0; nf < 4; nf++) {
                asm volatile(
                    "mma.sync.aligned.m16n8k16.row.col.f32.f16.f16.f32 "
                    "{%0,%1,%2,%3}, {%4,%5,%6,%7}, {%8,%9}, {%0,%1,%2,%3};\n"
                    : "+f"(acc[mf][nf][0]), "+f"(acc[mf][nf][1]),
                      "+f"(acc[mf][nf][2]), "+f"(acc[mf][nf][3])
                    : "r"(af[mf][0]), "r"(af[mf][1]), "r"(af[mf][2]), "r"(af[mf][3]),
                      "r"(bf[nf][0]), "r"(bf[nf][1]));
            }
        }
    }

#pragma unroll
    for (int mf = 0; mf < 4; mf++) {
#pragma unroll
        for (int nf = 0; nf < 4; nf++) {
            int row = row0 + mf * 16 + (lane >> 2);
            int col = wn + nf * 8 + (lane & 3) * 2;
            float b0 = bias[col], b1 = bias[col + 1];
            *reinterpret_cast<float2*>(Cout_ + (size_t)row * kCout + col) =
                make_float2(acc[mf][nf][0] + b0, acc[mf][nf][1] + b1);
            *reinterpret_cast<float2*>(Cout_ + (size_t)(row + 8) * kCout + col) =
                make_float2(acc[mf][nf][2] + b0, acc[mf][nf][3] + b1);
        }
    }
}

// --------------------------------- launcher ---------------------------------
extern "C" void kernel_launch(void* const* d_in, const int* in_sizes, int n_in,
                              void* d_out, int out_size) {
    const float* x   = (const float*)d_in[0];
    const float* Wx  = (const float*)d_in[1];
    const float* bx  = (const float*)d_in[2];
    const float* Wbc = (const float*)d_in[3];
    const float* bbc = (const float*)d_in[4];
    const float* Wd  = (const float*)d_in[5];
    const float* bd  = (const float*)d_in[6];
    const float* Wy  = (const float*)d_in[7];
    const float* by  = (const float*)d_in[8];
    float* out = (float*)d_out;
    (void)in_sizes; (void)n_in; (void)out_size;

    void *p_xp, *p_wp1, *p_wyp;
    cudaGetSymbolAddress(&p_xp,  g_xp);
    cudaGetSymbolAddress(&p_wp1, g_Wp1);
    cudaGetSymbolAddress(&p_wyp, g_Wyp);

    cudaFuncSetAttribute(gemm1_fused, cudaFuncAttributeMaxDynamicSharedMemorySize, GEMM1_SMEM);
    cudaFuncSetAttribute(gemm2f,      cudaFuncAttributeMaxDynamicSharedMemorySize, GEMM2_SMEM);

    pack_x_kernel <<<(kBL * 64) / 256, 256>>>(x);
    pack_w1_kernel<<<(256 * 2048) / 256, 256>>>(Wx, Wbc, Wd);
    pack_wy_kernel<<<(512 * 256) / 256, 256>>>(Wy);

    gemm1_fused<<<dim3(16, 128), 256, GEMM1_SMEM>>>(
        (const __half*)p_xp, (const __half*)p_wp1, bx, bbc, bd);

    scan_phase2<<<8, 256>>>();

    gemm2f<<<kNCHUNK, 256, GEMM2_SMEM>>>(
        (const __half*)p_wyp, by, out);
}